// round 1
// baseline (speedup 1.0000x reference)
#include <cuda_runtime.h>
#include <math.h>

#define BB 4
#define CC 512
#define SS 2048
#define HH 8
#define DD 64
#define NPB (CC*SS)   // elements per batch for GroupNorm (1,048,576)

// ---------------- scratch (static device memory; no allocs) ----------------
__device__ float g_part[128 * 2];          // per-(batch,chunk) partial sums
__device__ float g_stats[BB * 2];          // per-batch mean, inv_std
__device__ float g_h[BB * SS * CC];        // normalized, [B,S,C]
__device__ float g_q[BB * SS * CC];        // [B,H,S,D]
__device__ float g_k[BB * SS * CC];        // [B,H,S,D]
__device__ float g_v[BB * SS * CC];        // [B,H,S,D]
__device__ float g_o[BB * SS * CC];        // attention out, [B,S,C]

// ---------------- GroupNorm: deterministic two-pass reduction ----------------
__global__ void gn_partial(const float* __restrict__ x) {
    int b = blockIdx.x >> 5;
    int chunk = blockIdx.x & 31;
    const float* p = x + (size_t)b * NPB + (size_t)chunk * 32768;
    float s = 0.f, s2 = 0.f;
    for (int i = threadIdx.x; i < 32768; i += 256) {
        float v = p[i];
        s += v;
        s2 += v * v;
    }
    __shared__ float sh[256];
    __shared__ float sh2[256];
    sh[threadIdx.x] = s;
    sh2[threadIdx.x] = s2;
    __syncthreads();
    for (int off = 128; off > 0; off >>= 1) {
        if (threadIdx.x < off) {
            sh[threadIdx.x] += sh[threadIdx.x + off];
            sh2[threadIdx.x] += sh2[threadIdx.x + off];
        }
        __syncthreads();
    }
    if (threadIdx.x == 0) {
        g_part[blockIdx.x * 2 + 0] = sh[0];
        g_part[blockIdx.x * 2 + 1] = sh2[0];
    }
}

__global__ void gn_finalize() {
    int b = threadIdx.x;
    if (b < BB) {
        float s = 0.f, s2 = 0.f;
        for (int c = 0; c < 32; c++) {
            s  += g_part[(b * 32 + c) * 2 + 0];
            s2 += g_part[(b * 32 + c) * 2 + 1];
        }
        float mean = s / (float)NPB;
        float var = s2 / (float)NPB - mean * mean;
        g_stats[b * 2 + 0] = mean;
        g_stats[b * 2 + 1] = rsqrtf(var + 1e-5f);
    }
}

// ---------------- normalize + transpose [B,C,S] -> [B,S,C] ----------------
__global__ void norm_transpose(const float* __restrict__ x,
                               const float* __restrict__ gw,
                               const float* __restrict__ gb) {
    __shared__ float tile[32][33];
    int b = blockIdx.z;
    int c0 = blockIdx.y * 32;
    int s0 = blockIdx.x * 32;
    float mean = g_stats[b * 2 + 0];
    float inv  = g_stats[b * 2 + 1];
    int c = c0 + threadIdx.y;
    float scale = gw[c] * inv;
    float shift = gb[c] - mean * scale;
    float v = x[((size_t)b * CC + c) * SS + s0 + threadIdx.x];
    tile[threadIdx.y][threadIdx.x] = v * scale + shift;
    __syncthreads();
    g_h[((size_t)b * SS + s0 + threadIdx.y) * CC + c0 + threadIdx.x] =
        tile[threadIdx.x][threadIdx.y];
}

// ---------------- tiled NT SGEMM: C[m][n] = sum_k A[m][k] * W[n][k] ----------------
// M=8192, N=512, K=512. 64x64 tile, TK=32, 256 threads, 4x4 micro-tile.
// SRC_SEL: 0 -> g_h, 1 -> g_o
// DST_SEL: 0/1/2 -> g_q/g_k/g_v (scatter to [B,H,S,D]); 3 -> out ([B,C,S], +bias+residual)
template<int SRC_SEL, int DST_SEL>
__global__ void __launch_bounds__(256) gemm_nt(const float* __restrict__ W,
                                               const float* __restrict__ bias,
                                               const float* __restrict__ resid,
                                               float* __restrict__ out_param) {
    const float* A = (SRC_SEL == 0) ? g_h : g_o;
    float* out = (DST_SEL == 0) ? g_q : (DST_SEL == 1) ? g_k
               : (DST_SEL == 2) ? g_v : out_param;

    __shared__ float As[64 * 33];
    __shared__ float Bs[64 * 33];
    int tid = threadIdx.x;
    int tx = tid & 15;
    int ty = tid >> 4;
    int m0 = blockIdx.y * 64;
    int n0 = blockIdx.x * 64;

    float acc[4][4];
#pragma unroll
    for (int i = 0; i < 4; i++)
#pragma unroll
        for (int j = 0; j < 4; j++) acc[i][j] = 0.f;

    for (int kt = 0; kt < 512; kt += 32) {
#pragma unroll
        for (int r = 0; r < 2; r++) {
            int f = tid + r * 256;
            int row = f >> 3;
            int c4 = (f & 7) * 4;
            float4 av = *(const float4*)(A + (size_t)(m0 + row) * 512 + kt + c4);
            As[row * 33 + c4 + 0] = av.x;
            As[row * 33 + c4 + 1] = av.y;
            As[row * 33 + c4 + 2] = av.z;
            As[row * 33 + c4 + 3] = av.w;
            float4 wv = *(const float4*)(W + (size_t)(n0 + row) * 512 + kt + c4);
            Bs[row * 33 + c4 + 0] = wv.x;
            Bs[row * 33 + c4 + 1] = wv.y;
            Bs[row * 33 + c4 + 2] = wv.z;
            Bs[row * 33 + c4 + 3] = wv.w;
        }
        __syncthreads();
#pragma unroll
        for (int k = 0; k < 32; k++) {
            float a[4], bv[4];
#pragma unroll
            for (int i = 0; i < 4; i++) a[i] = As[(ty * 4 + i) * 33 + k];
#pragma unroll
            for (int j = 0; j < 4; j++) bv[j] = Bs[(tx * 4 + j) * 33 + k];
#pragma unroll
            for (int i = 0; i < 4; i++)
#pragma unroll
                for (int j = 0; j < 4; j++)
                    acc[i][j] += a[i] * bv[j];
        }
        __syncthreads();
    }

#pragma unroll
    for (int i = 0; i < 4; i++) {
#pragma unroll
        for (int j = 0; j < 4; j++) {
            int m = m0 + ty * 4 + i;
            int n = n0 + tx * 4 + j;
            float val = acc[i][j] + bias[n];
            int b = m >> 11;        // m / 2048
            int s = m & 2047;
            if (DST_SEL < 3) {
                int h = n >> 6;
                int d = n & 63;
                out[(((size_t)b * HH + h) * SS + s) * DD + d] = val;
            } else {
                size_t oi = ((size_t)b * CC + n) * SS + s;
                out[oi] = val + resid[oi];
            }
        }
    }
}

// ---------------- flash attention: one thread per query ----------------
// grid (S/128, B*H), 128 threads. 32-key K/V tiles in smem, online softmax.
__global__ void __launch_bounds__(128) attention_kernel() {
    __shared__ float Ks[32 * 64];
    __shared__ float Vs[32 * 64];
    int bh = blockIdx.y;
    int qi = blockIdx.x * 128 + threadIdx.x;

    const float* qp = g_q + ((size_t)bh * SS + qi) * DD;
    float q[DD], acc[DD];
#pragma unroll
    for (int d = 0; d < DD; d++) {
        q[d] = qp[d];
        acc[d] = 0.f;
    }
    float m = -1e30f, l = 0.f;

    const float4* kbase = (const float4*)(g_k + (size_t)bh * SS * DD);
    const float4* vbase = (const float4*)(g_v + (size_t)bh * SS * DD);
    float4* ksm = (float4*)Ks;
    float4* vsm = (float4*)Vs;

    for (int kt = 0; kt < SS; kt += 32) {
        __syncthreads();
        int base4 = kt * (DD / 4);   // float4 index of tile start
#pragma unroll
        for (int r = 0; r < 4; r++) {
            int f = threadIdx.x + r * 128;
            ksm[f] = kbase[base4 + f];
            vsm[f] = vbase[base4 + f];
        }
        __syncthreads();

        float s[32];
#pragma unroll
        for (int kk = 0; kk < 32; kk++) {
            float sv = 0.f;
            const float4* kr = (const float4*)(Ks + kk * 64);
#pragma unroll
            for (int d4 = 0; d4 < 16; d4++) {
                float4 kv = kr[d4];
                sv += q[d4 * 4 + 0] * kv.x;
                sv += q[d4 * 4 + 1] * kv.y;
                sv += q[d4 * 4 + 2] * kv.z;
                sv += q[d4 * 4 + 3] * kv.w;
            }
            s[kk] = sv * 0.125f;   // (1/D^0.25)^2 = 1/sqrt(64)
        }

        float tmax = s[0];
#pragma unroll
        for (int kk = 1; kk < 32; kk++) tmax = fmaxf(tmax, s[kk]);
        float mn = fmaxf(m, tmax);
        float corr = __expf(m - mn);
        l *= corr;
#pragma unroll
        for (int d = 0; d < DD; d++) acc[d] *= corr;

#pragma unroll
        for (int kk = 0; kk < 32; kk++) {
            float p = __expf(s[kk] - mn);
            l += p;
            const float4* vr = (const float4*)(Vs + kk * 64);
#pragma unroll
            for (int d4 = 0; d4 < 16; d4++) {
                float4 vv = vr[d4];
                acc[d4 * 4 + 0] += p * vv.x;
                acc[d4 * 4 + 1] += p * vv.y;
                acc[d4 * 4 + 2] += p * vv.z;
                acc[d4 * 4 + 3] += p * vv.w;
            }
        }
        m = mn;
    }

    float invl = 1.f / l;
    int b = bh >> 3;
    int h = bh & 7;
    float* op = g_o + ((size_t)b * SS + qi) * CC + h * DD;
#pragma unroll
    for (int d = 0; d < DD; d++) op[d] = acc[d] * invl;
}

// ---------------- launch ----------------
extern "C" void kernel_launch(void* const* d_in, const int* in_sizes, int n_in,
                              void* d_out, int out_size) {
    const float* x  = (const float*)d_in[0];
    const float* gw = (const float*)d_in[1];
    const float* gb = (const float*)d_in[2];
    const float* wq = (const float*)d_in[3];
    const float* bq = (const float*)d_in[4];
    const float* wk = (const float*)d_in[5];
    const float* bk = (const float*)d_in[6];
    const float* wv = (const float*)d_in[7];
    const float* bv = (const float*)d_in[8];
    const float* wo = (const float*)d_in[9];
    const float* bo = (const float*)d_in[10];
    float* out = (float*)d_out;

    gn_partial<<<128, 256>>>(x);
    gn_finalize<<<1, 32>>>();
    norm_transpose<<<dim3(SS / 32, CC / 32, BB), dim3(32, 32)>>>(x, gw, gb);

    dim3 ggrid(512 / 64, 8192 / 64);
    gemm_nt<0, 0><<<ggrid, 256>>>(wq, bq, nullptr, nullptr);
    gemm_nt<0, 1><<<ggrid, 256>>>(wk, bk, nullptr, nullptr);
    gemm_nt<0, 2><<<ggrid, 256>>>(wv, bv, nullptr, nullptr);

    attention_kernel<<<dim3(SS / 128, BB * HH), 128>>>();

    gemm_nt<1, 3><<<ggrid, 256>>>(wo, bo, x, out);
}

// round 3
// speedup vs baseline: 6.3748x; 6.3748x over previous
#include <cuda_runtime.h>
#include <cuda_bf16.h>
#include <cstdint>
#include <math.h>

#define BB 4
#define CC 512
#define SS 2048
#define HH 8
#define DD 64
#define NPB (CC*SS)

typedef __nv_bfloat16 bf16;

// ---------------- static device scratch ----------------
__device__ float g_part[128 * 2];
__device__ float g_stats[BB * 2];
__device__ bf16 g_h[BB * SS * CC];         // normalized, [B,S,C]
__device__ bf16 g_w[4 * CC * CC];          // wq,wk,wv,wo bf16
__device__ bf16 g_q[BB * HH * SS * DD];    // [B,H,S,D]
__device__ bf16 g_k[BB * HH * SS * DD];
__device__ bf16 g_v[BB * HH * SS * DD];
__device__ bf16 g_o[BB * SS * CC];         // attention out, [B,S,C]

// ---------------- low-level helpers ----------------
__device__ __forceinline__ uint32_t smem_u32(const void* p) {
    uint32_t a;
    asm("{ .reg .u64 t; cvta.to.shared.u64 t, %1; cvt.u32.u64 %0, t; }" : "=r"(a) : "l"(p));
    return a;
}
__device__ __forceinline__ void ldsm4(uint32_t* r, uint32_t addr) {
    asm volatile("ldmatrix.sync.aligned.m8n8.x4.shared.b16 {%0,%1,%2,%3}, [%4];"
                 : "=r"(r[0]), "=r"(r[1]), "=r"(r[2]), "=r"(r[3]) : "r"(addr));
}
__device__ __forceinline__ void ldsm4t(uint32_t* r, uint32_t addr) {
    asm volatile("ldmatrix.sync.aligned.m8n8.x4.trans.shared.b16 {%0,%1,%2,%3}, [%4];"
                 : "=r"(r[0]), "=r"(r[1]), "=r"(r[2]), "=r"(r[3]) : "r"(addr));
}
__device__ __forceinline__ void mma16816(float* c, const uint32_t* a, uint32_t b0, uint32_t b1) {
    asm volatile("mma.sync.aligned.m16n8k16.row.col.f32.bf16.bf16.f32 "
                 "{%0,%1,%2,%3}, {%4,%5,%6,%7}, {%8,%9}, {%0,%1,%2,%3};"
                 : "+f"(c[0]), "+f"(c[1]), "+f"(c[2]), "+f"(c[3])
                 : "r"(a[0]), "r"(a[1]), "r"(a[2]), "r"(a[3]), "r"(b0), "r"(b1));
}
__device__ __forceinline__ uint32_t pack_bf16x2(float lo, float hi) {
    uint32_t r;
    asm("cvt.rn.bf16x2.f32 %0, %1, %2;" : "=r"(r) : "f"(hi), "f"(lo));
    return r;
}

// ---------------- GroupNorm reductions ----------------
__global__ void gn_partial(const float* __restrict__ x) {
    int b = blockIdx.x >> 5;
    int chunk = blockIdx.x & 31;
    const float* p = x + (size_t)b * NPB + (size_t)chunk * 32768;
    float s = 0.f, s2 = 0.f;
    for (int i = threadIdx.x; i < 32768; i += 256) {
        float v = p[i];
        s += v; s2 += v * v;
    }
    __shared__ float sh[256], sh2[256];
    sh[threadIdx.x] = s; sh2[threadIdx.x] = s2;
    __syncthreads();
    for (int off = 128; off > 0; off >>= 1) {
        if (threadIdx.x < off) {
            sh[threadIdx.x] += sh[threadIdx.x + off];
            sh2[threadIdx.x] += sh2[threadIdx.x + off];
        }
        __syncthreads();
    }
    if (threadIdx.x == 0) {
        g_part[blockIdx.x * 2 + 0] = sh[0];
        g_part[blockIdx.x * 2 + 1] = sh2[0];
    }
}

__global__ void gn_finalize() {
    int b = threadIdx.x;
    if (b < BB) {
        float s = 0.f, s2 = 0.f;
        for (int c = 0; c < 32; c++) {
            s  += g_part[(b * 32 + c) * 2 + 0];
            s2 += g_part[(b * 32 + c) * 2 + 1];
        }
        float mean = s / (float)NPB;
        float var = s2 / (float)NPB - mean * mean;
        g_stats[b * 2 + 0] = mean;
        g_stats[b * 2 + 1] = rsqrtf(var + 1e-5f);
    }
}

// ---------------- normalize + transpose [B,C,S] -> bf16 [B,S,C] ----------------
__global__ void norm_convert(const float* __restrict__ x,
                             const float* __restrict__ gw,
                             const float* __restrict__ gb) {
    __shared__ float tile[32][33];
    int b = blockIdx.z;
    int c0 = blockIdx.y * 32;
    int s0 = blockIdx.x * 32;
    float mean = g_stats[b * 2 + 0];
    float inv  = g_stats[b * 2 + 1];
    int c = c0 + threadIdx.y;
    float scale = gw[c] * inv;
    float shift = gb[c] - mean * scale;
    float v = x[((size_t)b * CC + c) * SS + s0 + threadIdx.x];
    tile[threadIdx.y][threadIdx.x] = v * scale + shift;
    __syncthreads();
    g_h[((size_t)b * SS + s0 + threadIdx.y) * CC + c0 + threadIdx.x] =
        __float2bfloat16(tile[threadIdx.x][threadIdx.y]);
}

// ---------------- weights -> bf16 ----------------
__global__ void w_convert(const float* __restrict__ wq, const float* __restrict__ wk,
                          const float* __restrict__ wv, const float* __restrict__ wo) {
    int i = blockIdx.x * 256 + threadIdx.x;
    g_w[0 * CC * CC + i] = __float2bfloat16(wq[i]);
    g_w[1 * CC * CC + i] = __float2bfloat16(wk[i]);
    g_w[2 * CC * CC + i] = __float2bfloat16(wv[i]);
    g_w[3 * CC * CC + i] = __float2bfloat16(wo[i]);
}

// ---------------- HMMA NT GEMM: C[m,n] = sum_k A[m,k] W[n,k] + bias ----------------
// block tile 128(M) x 128(N), 256 threads (8 warps: 4M x 2N -> 32x64 warp tile).
// K loop: 16 tiles of 32. Padded smem stride 40 bf16 (80B) -> conflict-free ldmatrix.
#define GST 40

__device__ __forceinline__ void gemm_core(const bf16* __restrict__ A,
                                          const bf16* __restrict__ W,
                                          int m0, int n0, float c[2][8][4],
                                          bf16* As, bf16* Bs) {
    int tid = threadIdx.x;
    int lane = tid & 31;
    int wid = tid >> 5;
    int wm = wid >> 1, wn = wid & 1;
    uint32_t sA = smem_u32(As), sB = smem_u32(Bs);

#pragma unroll
    for (int i = 0; i < 2; i++)
#pragma unroll
        for (int j = 0; j < 8; j++)
#pragma unroll
            for (int k = 0; k < 4; k++) c[i][j][k] = 0.f;

    int r = tid >> 1, cseg = (tid & 1) * 16;

    for (int kt = 0; kt < 16; kt++) {
        const bf16* Ag = A + (size_t)(m0 + r) * 512 + kt * 32 + cseg;
        const bf16* Wg = W + (size_t)(n0 + r) * 512 + kt * 32 + cseg;
        uint4 a0 = *(const uint4*)(Ag);
        uint4 a1 = *(const uint4*)(Ag + 8);
        uint4 b0 = *(const uint4*)(Wg);
        uint4 b1 = *(const uint4*)(Wg + 8);
        *(uint4*)(As + r * GST + cseg) = a0;
        *(uint4*)(As + r * GST + cseg + 8) = a1;
        *(uint4*)(Bs + r * GST + cseg) = b0;
        *(uint4*)(Bs + r * GST + cseg + 8) = b1;
        __syncthreads();

#pragma unroll
        for (int ks = 0; ks < 2; ks++) {
            uint32_t a[2][4];
#pragma unroll
            for (int mt = 0; mt < 2; mt++) {
                uint32_t row = wm * 32 + mt * 16 + (lane & 15);
                uint32_t col = ks * 16 + (lane >> 4) * 8;
                ldsm4(a[mt], sA + (row * GST + col) * 2);
            }
#pragma unroll
            for (int p = 0; p < 4; p++) {
                uint32_t t4[4];
                uint32_t row = wn * 64 + p * 16 + (lane & 7) + ((lane >> 4) << 3);
                uint32_t col = ks * 16 + (((lane >> 3) & 1) << 3);
                ldsm4(t4, sB + (row * GST + col) * 2);
#pragma unroll
                for (int mt = 0; mt < 2; mt++) {
                    mma16816(c[mt][2 * p],     a[mt], t4[0], t4[1]);
                    mma16816(c[mt][2 * p + 1], a[mt], t4[2], t4[3]);
                }
            }
        }
        __syncthreads();
    }
}

// QKV projection: z selects weight/bias/dst. Output [B,H,S,D] bf16.
__global__ void __launch_bounds__(256) gemm_qkv(const float* __restrict__ bq,
                                                const float* __restrict__ bk,
                                                const float* __restrict__ bv) {
    __shared__ bf16 As[128 * GST];
    __shared__ bf16 Bs[128 * GST];
    int z = blockIdx.z;
    int m0 = blockIdx.y * 128, n0 = blockIdx.x * 128;
    const float* bias = (z == 0) ? bq : (z == 1) ? bk : bv;
    bf16* dst = (z == 0) ? g_q : (z == 1) ? g_k : g_v;

    float c[2][8][4];
    gemm_core(g_h, g_w + (size_t)z * CC * CC, m0, n0, c, As, Bs);

    int lane = threadIdx.x & 31;
    int wid = threadIdx.x >> 5;
    int wm = wid >> 1, wn = wid & 1;
#pragma unroll
    for (int mt = 0; mt < 2; mt++) {
        int r0 = m0 + wm * 32 + mt * 16 + (lane >> 2);
        int b0i = r0 >> 11, s0i = r0 & 2047;
        int r1 = r0 + 8;
        int b1i = r1 >> 11, s1i = r1 & 2047;
#pragma unroll
        for (int nt = 0; nt < 8; nt++) {
            int n = n0 + wn * 64 + nt * 8 + (lane & 3) * 2;
            float bv0 = bias[n], bv1 = bias[n + 1];
            int h = n >> 6, d = n & 63;
            uint32_t v0 = pack_bf16x2(c[mt][nt][0] + bv0, c[mt][nt][1] + bv1);
            uint32_t v1 = pack_bf16x2(c[mt][nt][2] + bv0, c[mt][nt][3] + bv1);
            *(uint32_t*)&dst[(((size_t)b0i * HH + h) * SS + s0i) * DD + d] = v0;
            *(uint32_t*)&dst[(((size_t)b1i * HH + h) * SS + s1i) * DD + d] = v1;
        }
    }
}

// Output projection: fp32 out [B,C,S] = A@wo^T + bo + residual
__global__ void __launch_bounds__(256) gemm_out(const float* __restrict__ bias,
                                                const float* __restrict__ resid,
                                                float* __restrict__ outp) {
    __shared__ bf16 As[128 * GST];
    __shared__ bf16 Bs[128 * GST];
    int m0 = blockIdx.y * 128, n0 = blockIdx.x * 128;

    float c[2][8][4];
    gemm_core(g_o, g_w + (size_t)3 * CC * CC, m0, n0, c, As, Bs);

    int lane = threadIdx.x & 31;
    int wid = threadIdx.x >> 5;
    int wm = wid >> 1, wn = wid & 1;
#pragma unroll
    for (int mt = 0; mt < 2; mt++) {
        int r0 = m0 + wm * 32 + mt * 16 + (lane >> 2);
#pragma unroll
        for (int half = 0; half < 2; half++) {
            int m = r0 + half * 8;
            int b = m >> 11, s = m & 2047;
#pragma unroll
            for (int nt = 0; nt < 8; nt++) {
                int n = n0 + wn * 64 + nt * 8 + (lane & 3) * 2;
                size_t oi0 = ((size_t)b * CC + n) * SS + s;
                size_t oi1 = oi0 + SS;
                outp[oi0] = c[mt][nt][2 * half + 0] + bias[n]     + resid[oi0];
                outp[oi1] = c[mt][nt][2 * half + 1] + bias[n + 1] + resid[oi1];
            }
        }
    }
}

// ---------------- HMMA flash attention (no-rescale softmax) ----------------
// CTA = 128 q rows of one (b,h); 8 warps x 16 q rows. Key tiles of 128.
// S frags exp'd + repacked directly as A frags of P@V (no smem round-trip).
#define AST 72
#define AQ_OFF 0
#define AK_OFF (128 * AST)
#define AV_OFF (256 * AST)
#define A_SMEM_BYTES (384 * AST * 2)

__global__ void __launch_bounds__(256) attn_mma() {
    extern __shared__ bf16 sm[];
    bf16* Qs = sm + AQ_OFF;
    bf16* Ks = sm + AK_OFF;
    bf16* Vs = sm + AV_OFF;
    uint32_t sQ = smem_u32(Qs), sK = smem_u32(Ks), sV = smem_u32(Vs);

    int tid = threadIdx.x;
    int lane = tid & 31;
    int wid = tid >> 5;
    int bh = blockIdx.y;
    int q0 = blockIdx.x * 128;

    const bf16* Qg = g_q + ((size_t)bh * SS + q0) * DD;
    const bf16* Kg = g_k + (size_t)bh * SS * DD;
    const bf16* Vg = g_v + (size_t)bh * SS * DD;

    int r = tid >> 1, cseg = (tid & 1) * 32;
    // load Q tile [128 x 64]
    {
        const uint4* src = (const uint4*)(Qg + (size_t)r * DD + cseg);
        uint4* dst = (uint4*)(Qs + r * AST + cseg);
        dst[0] = src[0]; dst[1] = src[1]; dst[2] = src[2]; dst[3] = src[3];
    }
    __syncthreads();

    // preload Q fragments (constant across key tiles)
    uint32_t aq[4][4];
#pragma unroll
    for (int ks = 0; ks < 4; ks++) {
        uint32_t row = wid * 16 + (lane & 15);
        uint32_t col = ks * 16 + (lane >> 4) * 8;
        ldsm4(aq[ks], sQ + (row * AST + col) * 2);
    }
    __syncthreads();

    float o[8][4];
#pragma unroll
    for (int i = 0; i < 8; i++)
#pragma unroll
        for (int j = 0; j < 4; j++) o[i][j] = 0.f;
    float l0 = 0.f, l1 = 0.f;

    for (int kt = 0; kt < 16; kt++) {
        // load K and V tiles [128 keys x 64 d]
        {
            const uint4* ks_ = (const uint4*)(Kg + ((size_t)(kt * 128) + r) * DD + cseg);
            const uint4* vs_ = (const uint4*)(Vg + ((size_t)(kt * 128) + r) * DD + cseg);
            uint4* kd = (uint4*)(Ks + r * AST + cseg);
            uint4* vd = (uint4*)(Vs + r * AST + cseg);
            kd[0] = ks_[0]; kd[1] = ks_[1]; kd[2] = ks_[2]; kd[3] = ks_[3];
            vd[0] = vs_[0]; vd[1] = vs_[1]; vd[2] = vs_[2]; vd[3] = vs_[3];
        }
        __syncthreads();

        // S = Q K^T : warp computes 16 x 128
        float c[16][4];
#pragma unroll
        for (int i = 0; i < 16; i++)
#pragma unroll
            for (int j = 0; j < 4; j++) c[i][j] = 0.f;
#pragma unroll
        for (int ks = 0; ks < 4; ks++) {
#pragma unroll
            for (int p = 0; p < 8; p++) {
                uint32_t t4[4];
                uint32_t row = p * 16 + (lane & 7) + ((lane >> 4) << 3);
                uint32_t col = ks * 16 + (((lane >> 3) & 1) << 3);
                ldsm4(t4, sK + (row * AST + col) * 2);
                mma16816(c[2 * p],     aq[ks], t4[0], t4[1]);
                mma16816(c[2 * p + 1], aq[ks], t4[2], t4[3]);
            }
        }

        // exp + pack as PV A-frags + accumulate l; then PV mma per k-step
#pragma unroll
        for (int s = 0; s < 8; s++) {
            float p00 = __expf(c[2 * s][0] * 0.125f);
            float p01 = __expf(c[2 * s][1] * 0.125f);
            float p02 = __expf(c[2 * s][2] * 0.125f);
            float p03 = __expf(c[2 * s][3] * 0.125f);
            float p10 = __expf(c[2 * s + 1][0] * 0.125f);
            float p11 = __expf(c[2 * s + 1][1] * 0.125f);
            float p12 = __expf(c[2 * s + 1][2] * 0.125f);
            float p13 = __expf(c[2 * s + 1][3] * 0.125f);
            l0 += p00 + p01 + p10 + p11;
            l1 += p02 + p03 + p12 + p13;
            uint32_t ap[4];
            ap[0] = pack_bf16x2(p00, p01);
            ap[1] = pack_bf16x2(p02, p03);
            ap[2] = pack_bf16x2(p10, p11);
            ap[3] = pack_bf16x2(p12, p13);
#pragma unroll
            for (int dp = 0; dp < 4; dp++) {
                uint32_t t4[4];
                uint32_t row = s * 16 + (lane & 15);
                uint32_t col = dp * 16 + (lane >> 4) * 8;
                ldsm4t(t4, sV + (row * AST + col) * 2);
                mma16816(o[2 * dp],     ap, t4[0], t4[1]);
                mma16816(o[2 * dp + 1], ap, t4[2], t4[3]);
            }
        }
        __syncthreads();
    }

    // reduce l over the 4-lane quad (lanes sharing a row)
    l0 += __shfl_xor_sync(0xFFFFFFFF, l0, 1);
    l0 += __shfl_xor_sync(0xFFFFFFFF, l0, 2);
    l1 += __shfl_xor_sync(0xFFFFFFFF, l1, 1);
    l1 += __shfl_xor_sync(0xFFFFFFFF, l1, 2);
    float invl0 = 1.f / l0, invl1 = 1.f / l1;

    // write O as bf16 to g_o [B,S,C]
    int b = bh >> 3, h = bh & 7;
    int row0 = q0 + wid * 16 + (lane >> 2);
    bf16* out0 = g_o + ((size_t)b * SS + row0) * CC + h * DD;
    bf16* out1 = g_o + ((size_t)b * SS + row0 + 8) * CC + h * DD;
#pragma unroll
    for (int nt = 0; nt < 8; nt++) {
        int d = nt * 8 + (lane & 3) * 2;
        *(uint32_t*)&out0[d] = pack_bf16x2(o[nt][0] * invl0, o[nt][1] * invl0);
        *(uint32_t*)&out1[d] = pack_bf16x2(o[nt][2] * invl1, o[nt][3] * invl1);
    }
}

// ---------------- launch ----------------
extern "C" void kernel_launch(void* const* d_in, const int* in_sizes, int n_in,
                              void* d_out, int out_size) {
    const float* x  = (const float*)d_in[0];
    const float* gw = (const float*)d_in[1];
    const float* gb = (const float*)d_in[2];
    const float* wq = (const float*)d_in[3];
    const float* bq = (const float*)d_in[4];
    const float* wk = (const float*)d_in[5];
    const float* bk = (const float*)d_in[6];
    const float* wv = (const float*)d_in[7];
    const float* bv = (const float*)d_in[8];
    const float* wo = (const float*)d_in[9];
    const float* bo = (const float*)d_in[10];
    float* out = (float*)d_out;

    static int configured = 0;
    if (!configured) {
        cudaFuncSetAttribute(attn_mma, cudaFuncAttributeMaxDynamicSharedMemorySize, A_SMEM_BYTES);
        configured = 1;
    }

    gn_partial<<<128, 256>>>(x);
    gn_finalize<<<1, 32>>>();
    norm_convert<<<dim3(SS / 32, CC / 32, BB), dim3(32, 32)>>>(x, gw, gb);
    w_convert<<<CC * CC / 256, 256>>>(wq, wk, wv, wo);

    gemm_qkv<<<dim3(CC / 128, BB * SS / 128, 3), 256>>>(bq, bk, bv);

    attn_mma<<<dim3(SS / 128, BB * HH), 256, A_SMEM_BYTES>>>();

    gemm_out<<<dim3(CC / 128, BB * SS / 128), 256>>>(bo, x, out);
}

// round 4
// speedup vs baseline: 6.3800x; 1.0008x over previous
#include <cuda_runtime.h>
#include <cuda_bf16.h>
#include <cstdint>
#include <math.h>

#define BB 4
#define CC 512
#define SS 2048
#define HH 8
#define DD 64
#define NPB (CC*SS)

typedef __nv_bfloat16 bf16;

// ---------------- static device scratch ----------------
__device__ float g_part[128 * 2];
__device__ float g_stats[BB * 2];
__device__ bf16 g_h[BB * SS * CC];         // normalized, [B,S,C]
__device__ bf16 g_w[4 * CC * CC];          // wq,wk,wv,wo bf16
__device__ bf16 g_q[BB * HH * SS * DD];    // [B,H,S,D]
__device__ bf16 g_k[BB * HH * SS * DD];
__device__ bf16 g_v[BB * HH * SS * DD];
__device__ bf16 g_o[BB * SS * CC];         // attention out, [B,S,C]

// ---------------- low-level helpers ----------------
__device__ __forceinline__ uint32_t smem_u32(const void* p) {
    uint32_t a;
    asm("{ .reg .u64 t; cvta.to.shared.u64 t, %1; cvt.u32.u64 %0, t; }" : "=r"(a) : "l"(p));
    return a;
}
__device__ __forceinline__ void ldsm4(uint32_t* r, uint32_t addr) {
    asm volatile("ldmatrix.sync.aligned.m8n8.x4.shared.b16 {%0,%1,%2,%3}, [%4];"
                 : "=r"(r[0]), "=r"(r[1]), "=r"(r[2]), "=r"(r[3]) : "r"(addr));
}
__device__ __forceinline__ void ldsm4t(uint32_t* r, uint32_t addr) {
    asm volatile("ldmatrix.sync.aligned.m8n8.x4.trans.shared.b16 {%0,%1,%2,%3}, [%4];"
                 : "=r"(r[0]), "=r"(r[1]), "=r"(r[2]), "=r"(r[3]) : "r"(addr));
}
__device__ __forceinline__ void mma16816(float* c, const uint32_t* a, uint32_t b0, uint32_t b1) {
    asm volatile("mma.sync.aligned.m16n8k16.row.col.f32.bf16.bf16.f32 "
                 "{%0,%1,%2,%3}, {%4,%5,%6,%7}, {%8,%9}, {%0,%1,%2,%3};"
                 : "+f"(c[0]), "+f"(c[1]), "+f"(c[2]), "+f"(c[3])
                 : "r"(a[0]), "r"(a[1]), "r"(a[2]), "r"(a[3]), "r"(b0), "r"(b1));
}
__device__ __forceinline__ uint32_t pack_bf16x2(float lo, float hi) {
    uint32_t r;
    asm("cvt.rn.bf16x2.f32 %0, %1, %2;" : "=r"(r) : "f"(hi), "f"(lo));
    return r;
}
__device__ __forceinline__ void cp16(uint32_t dst, const void* src) {
    asm volatile("cp.async.cg.shared.global [%0], [%1], 16;" :: "r"(dst), "l"(src));
}
#define CP_COMMIT() asm volatile("cp.async.commit_group;" ::: "memory")
#define CP_WAIT0()  asm volatile("cp.async.wait_group 0;" ::: "memory")

// fast exp on fma/alu pipes (no MUFU). exp(x) = 2^(x*log2e).
// arg pre-scaled by caller; |x*log2e| << 2^21 always true here.
__device__ __forceinline__ float fexp_t(float t) {   // t = x * log2(e)
    float z = t + 12582912.f;                        // round-to-nearest via magic
    float n = z - 12582912.f;
    float f = t - n;                                 // f in [-0.5, 0.5]
    float p = 1.3333558146e-3f;
    p = fmaf(p, f, 9.6181291076e-3f);
    p = fmaf(p, f, 5.5504108664e-2f);
    p = fmaf(p, f, 2.4022650696e-1f);
    p = fmaf(p, f, 6.9314718056e-1f);
    p = fmaf(p, f, 1.0f);
    uint32_t r = __float_as_uint(p) + (__float_as_uint(z) << 23);
    return __uint_as_float(r);
}
#define SCALE_LOG2E 0.1803368801111204f   // 0.125 * log2(e)

// ---------------- GroupNorm reductions ----------------
__global__ void gn_partial(const float* __restrict__ x) {
    int b = blockIdx.x >> 5;
    int chunk = blockIdx.x & 31;
    const float* p = x + (size_t)b * NPB + (size_t)chunk * 32768;
    float s = 0.f, s2 = 0.f;
    for (int i = threadIdx.x; i < 32768; i += 256) {
        float v = p[i];
        s += v; s2 += v * v;
    }
    __shared__ float sh[256], sh2[256];
    sh[threadIdx.x] = s; sh2[threadIdx.x] = s2;
    __syncthreads();
    for (int off = 128; off > 0; off >>= 1) {
        if (threadIdx.x < off) {
            sh[threadIdx.x] += sh[threadIdx.x + off];
            sh2[threadIdx.x] += sh2[threadIdx.x + off];
        }
        __syncthreads();
    }
    if (threadIdx.x == 0) {
        g_part[blockIdx.x * 2 + 0] = sh[0];
        g_part[blockIdx.x * 2 + 1] = sh2[0];
    }
}

__global__ void gn_finalize() {
    int b = threadIdx.x;
    if (b < BB) {
        float s = 0.f, s2 = 0.f;
        for (int c = 0; c < 32; c++) {
            s  += g_part[(b * 32 + c) * 2 + 0];
            s2 += g_part[(b * 32 + c) * 2 + 1];
        }
        float mean = s / (float)NPB;
        float var = s2 / (float)NPB - mean * mean;
        g_stats[b * 2 + 0] = mean;
        g_stats[b * 2 + 1] = rsqrtf(var + 1e-5f);
    }
}

// ---------------- normalize + transpose [B,C,S] -> bf16 [B,S,C] ----------------
__global__ void norm_convert(const float* __restrict__ x,
                             const float* __restrict__ gw,
                             const float* __restrict__ gb) {
    __shared__ float tile[32][33];
    int b = blockIdx.z;
    int c0 = blockIdx.y * 32;
    int s0 = blockIdx.x * 32;
    float mean = g_stats[b * 2 + 0];
    float inv  = g_stats[b * 2 + 1];
    int c = c0 + threadIdx.y;
    float scale = gw[c] * inv;
    float shift = gb[c] - mean * scale;
    float v = x[((size_t)b * CC + c) * SS + s0 + threadIdx.x];
    tile[threadIdx.y][threadIdx.x] = v * scale + shift;
    __syncthreads();
    g_h[((size_t)b * SS + s0 + threadIdx.y) * CC + c0 + threadIdx.x] =
        __float2bfloat16(tile[threadIdx.x][threadIdx.y]);
}

// ---------------- weights -> bf16 ----------------
__global__ void w_convert(const float* __restrict__ wq, const float* __restrict__ wk,
                          const float* __restrict__ wv, const float* __restrict__ wo) {
    int i = blockIdx.x * 256 + threadIdx.x;
    g_w[0 * CC * CC + i] = __float2bfloat16(wq[i]);
    g_w[1 * CC * CC + i] = __float2bfloat16(wk[i]);
    g_w[2 * CC * CC + i] = __float2bfloat16(wv[i]);
    g_w[3 * CC * CC + i] = __float2bfloat16(wo[i]);
}

// ---------------- HMMA NT GEMM, cp.async double-buffered ----------------
// block tile 128(M) x 128(N), 256 threads (8 warps: 4M x 2N -> 32x64 warp tile).
// K loop: 16 tiles of 32. Padded smem stride 40 bf16 -> conflict-free ldmatrix.
#define GST 40
#define GTILE (128 * GST)          // elements per buffer

__device__ __forceinline__ void gemm_core(const bf16* __restrict__ A,
                                          const bf16* __restrict__ W,
                                          int m0, int n0, float c[2][8][4],
                                          bf16* As, bf16* Bs) {
    int tid = threadIdx.x;
    int lane = tid & 31;
    int wid = tid >> 5;
    int wm = wid >> 1, wn = wid & 1;
    uint32_t sA = smem_u32(As), sB = smem_u32(Bs);

#pragma unroll
    for (int i = 0; i < 2; i++)
#pragma unroll
        for (int j = 0; j < 8; j++)
#pragma unroll
            for (int k = 0; k < 4; k++) c[i][j][k] = 0.f;

    int r = tid >> 1, cseg = (tid & 1) * 16;
    const bf16* Ag = A + (size_t)(m0 + r) * 512 + cseg;
    const bf16* Wg = W + (size_t)(n0 + r) * 512 + cseg;
    uint32_t dOff = (uint32_t)(r * GST + cseg) * 2;

    // prefetch tile 0 into buffer 0
    cp16(sA + dOff,      Ag);
    cp16(sA + dOff + 16, Ag + 8);
    cp16(sB + dOff,      Wg);
    cp16(sB + dOff + 16, Wg + 8);
    CP_COMMIT();

    for (int kt = 0; kt < 16; kt++) {
        uint32_t bo = (uint32_t)(kt & 1) * (GTILE * 2);
        CP_WAIT0();
        __syncthreads();
        if (kt < 15) {
            uint32_t bn = (uint32_t)((kt + 1) & 1) * (GTILE * 2);
            const bf16* An = Ag + (kt + 1) * 32;
            const bf16* Wn = Wg + (kt + 1) * 32;
            cp16(sA + bn + dOff,      An);
            cp16(sA + bn + dOff + 16, An + 8);
            cp16(sB + bn + dOff,      Wn);
            cp16(sB + bn + dOff + 16, Wn + 8);
            CP_COMMIT();
        }
#pragma unroll
        for (int ks = 0; ks < 2; ks++) {
            uint32_t a[2][4];
#pragma unroll
            for (int mt = 0; mt < 2; mt++) {
                uint32_t row = wm * 32 + mt * 16 + (lane & 15);
                uint32_t col = ks * 16 + (lane >> 4) * 8;
                ldsm4(a[mt], sA + bo + (row * GST + col) * 2);
            }
#pragma unroll
            for (int p = 0; p < 4; p++) {
                uint32_t t4[4];
                uint32_t row = wn * 64 + p * 16 + (lane & 7) + ((lane >> 4) << 3);
                uint32_t col = ks * 16 + (((lane >> 3) & 1) << 3);
                ldsm4(t4, sB + bo + (row * GST + col) * 2);
#pragma unroll
                for (int mt = 0; mt < 2; mt++) {
                    mma16816(c[mt][2 * p],     a[mt], t4[0], t4[1]);
                    mma16816(c[mt][2 * p + 1], a[mt], t4[2], t4[3]);
                }
            }
        }
        __syncthreads();
    }
}

// QKV projection: z selects weight/bias/dst. Output [B,H,S,D] bf16.
__global__ void __launch_bounds__(256, 2) gemm_qkv(const float* __restrict__ bq,
                                                   const float* __restrict__ bk,
                                                   const float* __restrict__ bv) {
    __shared__ bf16 As[2 * GTILE];
    __shared__ bf16 Bs[2 * GTILE];
    int z = blockIdx.z;
    int m0 = blockIdx.y * 128, n0 = blockIdx.x * 128;
    const float* bias = (z == 0) ? bq : (z == 1) ? bk : bv;
    bf16* dst = (z == 0) ? g_q : (z == 1) ? g_k : g_v;

    float c[2][8][4];
    gemm_core(g_h, g_w + (size_t)z * CC * CC, m0, n0, c, As, Bs);

    int lane = threadIdx.x & 31;
    int wid = threadIdx.x >> 5;
    int wm = wid >> 1, wn = wid & 1;
#pragma unroll
    for (int mt = 0; mt < 2; mt++) {
        int r0 = m0 + wm * 32 + mt * 16 + (lane >> 2);
        int b0i = r0 >> 11, s0i = r0 & 2047;
        int r1 = r0 + 8;
        int b1i = r1 >> 11, s1i = r1 & 2047;
#pragma unroll
        for (int nt = 0; nt < 8; nt++) {
            int n = n0 + wn * 64 + nt * 8 + (lane & 3) * 2;
            float bv0 = bias[n], bv1 = bias[n + 1];
            int h = n >> 6, d = n & 63;
            uint32_t v0 = pack_bf16x2(c[mt][nt][0] + bv0, c[mt][nt][1] + bv1);
            uint32_t v1 = pack_bf16x2(c[mt][nt][2] + bv0, c[mt][nt][3] + bv1);
            *(uint32_t*)&dst[(((size_t)b0i * HH + h) * SS + s0i) * DD + d] = v0;
            *(uint32_t*)&dst[(((size_t)b1i * HH + h) * SS + s1i) * DD + d] = v1;
        }
    }
}

// Output projection: fp32 out [B,C,S] = A@wo^T + bo + residual
__global__ void __launch_bounds__(256, 2) gemm_out(const float* __restrict__ bias,
                                                   const float* __restrict__ resid,
                                                   float* __restrict__ outp) {
    __shared__ bf16 As[2 * GTILE];
    __shared__ bf16 Bs[2 * GTILE];
    int m0 = blockIdx.y * 128, n0 = blockIdx.x * 128;

    float c[2][8][4];
    gemm_core(g_o, g_w + (size_t)3 * CC * CC, m0, n0, c, As, Bs);

    int lane = threadIdx.x & 31;
    int wid = threadIdx.x >> 5;
    int wm = wid >> 1, wn = wid & 1;
#pragma unroll
    for (int mt = 0; mt < 2; mt++) {
        int r0 = m0 + wm * 32 + mt * 16 + (lane >> 2);
#pragma unroll
        for (int half = 0; half < 2; half++) {
            int m = r0 + half * 8;
            int b = m >> 11, s = m & 2047;
#pragma unroll
            for (int nt = 0; nt < 8; nt++) {
                int n = n0 + wn * 64 + nt * 8 + (lane & 3) * 2;
                size_t oi0 = ((size_t)b * CC + n) * SS + s;
                size_t oi1 = oi0 + SS;
                outp[oi0] = c[mt][nt][2 * half + 0] + bias[n]     + resid[oi0];
                outp[oi1] = c[mt][nt][2 * half + 1] + bias[n + 1] + resid[oi1];
            }
        }
    }
}

// ---------------- HMMA flash attention (no-rescale softmax) ----------------
// CTA = 128 q rows of one (b,h); 8 warps x 16 q rows. 128-key tiles,
// cp.async double-buffered K/V. S-slab (16 keys) processed end-to-end:
// QK mma -> fma-pipe exp -> pack as PV A-frags -> PV mma. No smem round-trip.
#define AST 72
#define ATILE (128 * AST)          // elements per K or V buffer
#define A_SMEM_BYTES (5 * ATILE * 2)

__global__ void __launch_bounds__(256, 2) attn_mma() {
    extern __shared__ bf16 sm[];
    bf16* Qs = sm;
    uint32_t sQ = smem_u32(Qs);
    uint32_t sK = sQ + ATILE * 2;      // buffers: K0,K1,V0,V1
    uint32_t sV = sQ + 3 * ATILE * 2;

    int tid = threadIdx.x;
    int lane = tid & 31;
    int wid = tid >> 5;
    int bh = blockIdx.y;
    int q0 = blockIdx.x * 128;

    const bf16* Qg = g_q + ((size_t)bh * SS + q0) * DD;
    const bf16* Kg = g_k + (size_t)bh * SS * DD;
    const bf16* Vg = g_v + (size_t)bh * SS * DD;

    int r = tid >> 1, cseg = (tid & 1) * 32;
    uint32_t dOff = (uint32_t)(r * AST + cseg) * 2;
    const bf16* Kt = Kg + (size_t)r * DD + cseg;
    const bf16* Vt = Vg + (size_t)r * DD + cseg;

    // prefetch K/V tile 0 into buffer 0 (4 x 16B each)
#pragma unroll
    for (int j = 0; j < 4; j++) {
        cp16(sK + dOff + j * 16, Kt + j * 8);
        cp16(sV + dOff + j * 16, Vt + j * 8);
    }
    CP_COMMIT();

    // load Q tile [128 x 64]
    {
        const uint4* src = (const uint4*)(Qg + (size_t)r * DD + cseg);
        uint4* dst = (uint4*)((char*)Qs + dOff);
        dst[0] = src[0]; dst[1] = src[1]; dst[2] = src[2]; dst[3] = src[3];
    }
    __syncthreads();

    // preload Q fragments (constant across key tiles)
    uint32_t aq[4][4];
#pragma unroll
    for (int ks = 0; ks < 4; ks++) {
        uint32_t row = wid * 16 + (lane & 15);
        uint32_t col = ks * 16 + (lane >> 4) * 8;
        ldsm4(aq[ks], sQ + (row * AST + col) * 2);
    }

    float o[8][4];
#pragma unroll
    for (int i = 0; i < 8; i++)
#pragma unroll
        for (int j = 0; j < 4; j++) o[i][j] = 0.f;
    float l0 = 0.f, l1 = 0.f;

    for (int kt = 0; kt < 16; kt++) {
        uint32_t bo = (uint32_t)(kt & 1) * (ATILE * 2);
        CP_WAIT0();
        __syncthreads();
        if (kt < 15) {
            uint32_t bn = (uint32_t)((kt + 1) & 1) * (ATILE * 2);
            const bf16* Kn = Kt + (size_t)(kt + 1) * 128 * DD;
            const bf16* Vn = Vt + (size_t)(kt + 1) * 128 * DD;
#pragma unroll
            for (int j = 0; j < 4; j++) {
                cp16(sK + bn + dOff + j * 16, Kn + j * 8);
                cp16(sV + bn + dOff + j * 16, Vn + j * 8);
            }
            CP_COMMIT();
        }

#pragma unroll
        for (int s = 0; s < 8; s++) {
            // S-slab: 16 q rows x 16 keys
            float c0[4] = {0.f, 0.f, 0.f, 0.f};
            float c1[4] = {0.f, 0.f, 0.f, 0.f};
#pragma unroll
            for (int ks = 0; ks < 4; ks++) {
                uint32_t t4[4];
                uint32_t row = s * 16 + (lane & 7) + ((lane >> 4) << 3);
                uint32_t col = ks * 16 + (((lane >> 3) & 1) << 3);
                ldsm4(t4, sK + bo + (row * AST + col) * 2);
                mma16816(c0, aq[ks], t4[0], t4[1]);
                mma16816(c1, aq[ks], t4[2], t4[3]);
            }
            float p00 = fexp_t(c0[0] * SCALE_LOG2E);
            float p01 = fexp_t(c0[1] * SCALE_LOG2E);
            float p02 = fexp_t(c0[2] * SCALE_LOG2E);
            float p03 = fexp_t(c0[3] * SCALE_LOG2E);
            float p10 = fexp_t(c1[0] * SCALE_LOG2E);
            float p11 = fexp_t(c1[1] * SCALE_LOG2E);
            float p12 = fexp_t(c1[2] * SCALE_LOG2E);
            float p13 = fexp_t(c1[3] * SCALE_LOG2E);
            l0 += p00 + p01 + p10 + p11;
            l1 += p02 + p03 + p12 + p13;
            uint32_t ap[4];
            ap[0] = pack_bf16x2(p00, p01);
            ap[1] = pack_bf16x2(p02, p03);
            ap[2] = pack_bf16x2(p10, p11);
            ap[3] = pack_bf16x2(p12, p13);
#pragma unroll
            for (int dp = 0; dp < 4; dp++) {
                uint32_t t4[4];
                uint32_t row = s * 16 + (lane & 15);
                uint32_t col = dp * 16 + (lane >> 4) * 8;
                ldsm4t(t4, sV + bo + (row * AST + col) * 2);
                mma16816(o[2 * dp],     ap, t4[0], t4[1]);
                mma16816(o[2 * dp + 1], ap, t4[2], t4[3]);
            }
        }
        __syncthreads();
    }

    // reduce l over the 4-lane quad (lanes sharing a row)
    l0 += __shfl_xor_sync(0xFFFFFFFF, l0, 1);
    l0 += __shfl_xor_sync(0xFFFFFFFF, l0, 2);
    l1 += __shfl_xor_sync(0xFFFFFFFF, l1, 1);
    l1 += __shfl_xor_sync(0xFFFFFFFF, l1, 2);
    float invl0 = 1.f / l0, invl1 = 1.f / l1;

    // write O as bf16 to g_o [B,S,C]
    int b = bh >> 3, h = bh & 7;
    int row0 = q0 + wid * 16 + (lane >> 2);
    bf16* out0 = g_o + ((size_t)b * SS + row0) * CC + h * DD;
    bf16* out1 = g_o + ((size_t)b * SS + row0 + 8) * CC + h * DD;
#pragma unroll
    for (int nt = 0; nt < 8; nt++) {
        int d = nt * 8 + (lane & 3) * 2;
        *(uint32_t*)&out0[d] = pack_bf16x2(o[nt][0] * invl0, o[nt][1] * invl0);
        *(uint32_t*)&out1[d] = pack_bf16x2(o[nt][2] * invl1, o[nt][3] * invl1);
    }
}

// ---------------- launch ----------------
extern "C" void kernel_launch(void* const* d_in, const int* in_sizes, int n_in,
                              void* d_out, int out_size) {
    const float* x  = (const float*)d_in[0];
    const float* gw = (const float*)d_in[1];
    const float* gb = (const float*)d_in[2];
    const float* wq = (const float*)d_in[3];
    const float* bq = (const float*)d_in[4];
    const float* wk = (const float*)d_in[5];
    const float* bk = (const float*)d_in[6];
    const float* wv = (const float*)d_in[7];
    const float* bv = (const float*)d_in[8];
    const float* wo = (const float*)d_in[9];
    const float* bo = (const float*)d_in[10];
    float* out = (float*)d_out;

    cudaFuncSetAttribute(attn_mma, cudaFuncAttributeMaxDynamicSharedMemorySize, A_SMEM_BYTES);

    gn_partial<<<128, 256>>>(x);
    gn_finalize<<<1, 32>>>();
    norm_convert<<<dim3(SS / 32, CC / 32, BB), dim3(32, 32)>>>(x, gw, gb);
    w_convert<<<CC * CC / 256, 256>>>(wq, wk, wv, wo);

    gemm_qkv<<<dim3(CC / 128, BB * SS / 128, 3), 256>>>(bq, bk, bv);

    attn_mma<<<dim3(SS / 128, BB * HH), 256, A_SMEM_BYTES>>>();

    gemm_out<<<dim3(CC / 128, BB * SS / 128), 256>>>(bo, x, out);
}

// round 5
// speedup vs baseline: 7.0909x; 1.1114x over previous
#include <cuda_runtime.h>
#include <cuda_bf16.h>
#include <cstdint>
#include <math.h>

#define BB 4
#define CC 512
#define SS 2048
#define HH 8
#define DD 64
#define NPB (CC*SS)

typedef __nv_bfloat16 bf16;

// Q pre-scale: 0.125 (attention scale) * log2(e) so softmax = ex2(score)
#define QPRESCALE 0.18033688011112042f

// ---------------- static device scratch ----------------
__device__ float g_part[128 * 2];
__device__ float g_stats[BB * 2];
__device__ bf16 g_h[BB * SS * CC];         // normalized, [B,S,C]
__device__ bf16 g_w[4 * CC * CC];          // wq,wk,wv,wo bf16
__device__ bf16 g_q[BB * HH * SS * DD];    // [B,H,S,D] (pre-scaled)
__device__ bf16 g_k[BB * HH * SS * DD];
__device__ bf16 g_v[BB * HH * SS * DD];
__device__ bf16 g_o[BB * SS * CC];         // attention out, [B,S,C]

// ---------------- low-level helpers ----------------
__device__ __forceinline__ uint32_t smem_u32(const void* p) {
    uint32_t a;
    asm("{ .reg .u64 t; cvta.to.shared.u64 t, %1; cvt.u32.u64 %0, t; }" : "=r"(a) : "l"(p));
    return a;
}
__device__ __forceinline__ void ldsm4(uint32_t* r, uint32_t addr) {
    asm volatile("ldmatrix.sync.aligned.m8n8.x4.shared.b16 {%0,%1,%2,%3}, [%4];"
                 : "=r"(r[0]), "=r"(r[1]), "=r"(r[2]), "=r"(r[3]) : "r"(addr));
}
__device__ __forceinline__ void ldsm4t(uint32_t* r, uint32_t addr) {
    asm volatile("ldmatrix.sync.aligned.m8n8.x4.trans.shared.b16 {%0,%1,%2,%3}, [%4];"
                 : "=r"(r[0]), "=r"(r[1]), "=r"(r[2]), "=r"(r[3]) : "r"(addr));
}
__device__ __forceinline__ void mma16816(float* c, const uint32_t* a, uint32_t b0, uint32_t b1) {
    asm volatile("mma.sync.aligned.m16n8k16.row.col.f32.bf16.bf16.f32 "
                 "{%0,%1,%2,%3}, {%4,%5,%6,%7}, {%8,%9}, {%0,%1,%2,%3};"
                 : "+f"(c[0]), "+f"(c[1]), "+f"(c[2]), "+f"(c[3])
                 : "r"(a[0]), "r"(a[1]), "r"(a[2]), "r"(a[3]), "r"(b0), "r"(b1));
}
__device__ __forceinline__ uint32_t pack_bf16x2(float lo, float hi) {
    uint32_t r;
    asm("cvt.rn.bf16x2.f32 %0, %1, %2;" : "=r"(r) : "f"(hi), "f"(lo));
    return r;
}
__device__ __forceinline__ float ex2(float x) {
    float r;
    asm("ex2.approx.f32 %0, %1;" : "=f"(r) : "f"(x));
    return r;
}
__device__ __forceinline__ void cp16(uint32_t dst, const void* src) {
    asm volatile("cp.async.cg.shared.global [%0], [%1], 16;" :: "r"(dst), "l"(src));
}
#define CP_COMMIT() asm volatile("cp.async.commit_group;" ::: "memory")
#define CP_WAIT0()  asm volatile("cp.async.wait_group 0;" ::: "memory")
#define CP_WAIT2()  asm volatile("cp.async.wait_group 2;" ::: "memory")

// ---------------- GroupNorm reductions ----------------
__global__ void gn_partial(const float* __restrict__ x) {
    int b = blockIdx.x >> 5;
    int chunk = blockIdx.x & 31;
    const float4* p = (const float4*)(x + (size_t)b * NPB + (size_t)chunk * 32768);
    float s = 0.f, s2 = 0.f;
    for (int i = threadIdx.x; i < 8192; i += 256) {
        float4 v = p[i];
        s += v.x + v.y + v.z + v.w;
        s2 += v.x * v.x + v.y * v.y + v.z * v.z + v.w * v.w;
    }
    __shared__ float sh[256], sh2[256];
    sh[threadIdx.x] = s; sh2[threadIdx.x] = s2;
    __syncthreads();
    for (int off = 128; off > 0; off >>= 1) {
        if (threadIdx.x < off) {
            sh[threadIdx.x] += sh[threadIdx.x + off];
            sh2[threadIdx.x] += sh2[threadIdx.x + off];
        }
        __syncthreads();
    }
    if (threadIdx.x == 0) {
        g_part[blockIdx.x * 2 + 0] = sh[0];
        g_part[blockIdx.x * 2 + 1] = sh2[0];
    }
}

__global__ void gn_finalize() {
    int b = threadIdx.x;
    if (b < BB) {
        float s = 0.f, s2 = 0.f;
        for (int c = 0; c < 32; c++) {
            s  += g_part[(b * 32 + c) * 2 + 0];
            s2 += g_part[(b * 32 + c) * 2 + 1];
        }
        float mean = s / (float)NPB;
        float var = s2 / (float)NPB - mean * mean;
        g_stats[b * 2 + 0] = mean;
        g_stats[b * 2 + 1] = rsqrtf(var + 1e-5f);
    }
}

// ---------------- normalize + transpose [B,C,S] -> bf16 [B,S,C] ----------------
__global__ void norm_convert(const float* __restrict__ x,
                             const float* __restrict__ gw,
                             const float* __restrict__ gb) {
    __shared__ float tile[32][33];
    int b = blockIdx.z;
    int c0 = blockIdx.y * 32;
    int s0 = blockIdx.x * 32;
    float mean = g_stats[b * 2 + 0];
    float inv  = g_stats[b * 2 + 1];
    int c = c0 + threadIdx.y;
    float scale = gw[c] * inv;
    float shift = gb[c] - mean * scale;
    float v = x[((size_t)b * CC + c) * SS + s0 + threadIdx.x];
    tile[threadIdx.y][threadIdx.x] = v * scale + shift;
    __syncthreads();
    g_h[((size_t)b * SS + s0 + threadIdx.y) * CC + c0 + threadIdx.x] =
        __float2bfloat16(tile[threadIdx.x][threadIdx.y]);
}

// ---------------- weights -> bf16 ----------------
__global__ void w_convert(const float* __restrict__ wq, const float* __restrict__ wk,
                          const float* __restrict__ wv, const float* __restrict__ wo) {
    int i = blockIdx.x * 256 + threadIdx.x;
    g_w[0 * CC * CC + i] = __float2bfloat16(wq[i]);
    g_w[1 * CC * CC + i] = __float2bfloat16(wk[i]);
    g_w[2 * CC * CC + i] = __float2bfloat16(wv[i]);
    g_w[3 * CC * CC + i] = __float2bfloat16(wo[i]);
}

// ---------------- HMMA NT GEMM, 4-stage cp.async pipeline ----------------
// block tile 128(M) x 128(N), 256 threads (8 warps: 4M x 2N -> 32x64 warp tile).
// 16 K-tiles of 32. Padded smem stride 40 bf16 -> conflict-free ldmatrix.
#define GST 40
#define GTB (128 * GST * 2)       // bytes per buffer per matrix (10240)
#define G_SMEM_BYTES (8 * GTB)    // A[4 stages] + B[4 stages]

__device__ __forceinline__ void gemm_core(const bf16* __restrict__ A,
                                          const bf16* __restrict__ W,
                                          int m0, int n0, float c[2][8][4],
                                          char* smem) {
    int tid = threadIdx.x;
    int lane = tid & 31;
    int wid = tid >> 5;
    int wm = wid >> 1, wn = wid & 1;
    uint32_t sA = smem_u32(smem);
    uint32_t sB = sA + 4 * GTB;

#pragma unroll
    for (int i = 0; i < 2; i++)
#pragma unroll
        for (int j = 0; j < 8; j++)
#pragma unroll
            for (int k = 0; k < 4; k++) c[i][j][k] = 0.f;

    int r = tid >> 1, cseg = (tid & 1) * 16;
    const bf16* Ag = A + (size_t)(m0 + r) * 512 + cseg;
    const bf16* Wg = W + (size_t)(n0 + r) * 512 + cseg;
    uint32_t dOff = (uint32_t)(r * GST + cseg) * 2;

#define GPF(kt) do { \
        uint32_t _b = (uint32_t)((kt) & 3) * GTB; \
        const bf16* _An = Ag + (kt) * 32; \
        const bf16* _Wn = Wg + (kt) * 32; \
        cp16(sA + _b + dOff,      _An); \
        cp16(sA + _b + dOff + 16, _An + 8); \
        cp16(sB + _b + dOff,      _Wn); \
        cp16(sB + _b + dOff + 16, _Wn + 8); \
        CP_COMMIT(); \
    } while (0)

    GPF(0); GPF(1); GPF(2);

    for (int kt = 0; kt < 16; kt++) {
        CP_WAIT2();
        __syncthreads();
        if (kt < 13) GPF(kt + 3); else CP_COMMIT();
        uint32_t bo = (uint32_t)(kt & 3) * GTB;
#pragma unroll
        for (int ks = 0; ks < 2; ks++) {
            uint32_t a[2][4];
#pragma unroll
            for (int mt = 0; mt < 2; mt++) {
                uint32_t row = wm * 32 + mt * 16 + (lane & 15);
                uint32_t col = ks * 16 + (lane >> 4) * 8;
                ldsm4(a[mt], sA + bo + (row * GST + col) * 2);
            }
#pragma unroll
            for (int p = 0; p < 4; p++) {
                uint32_t t4[4];
                uint32_t row = wn * 64 + p * 16 + (lane & 7) + ((lane >> 4) << 3);
                uint32_t col = ks * 16 + (((lane >> 3) & 1) << 3);
                ldsm4(t4, sB + bo + (row * GST + col) * 2);
#pragma unroll
                for (int mt = 0; mt < 2; mt++) {
                    mma16816(c[mt][2 * p],     a[mt], t4[0], t4[1]);
                    mma16816(c[mt][2 * p + 1], a[mt], t4[2], t4[3]);
                }
            }
        }
    }
#undef GPF
}

// QKV projection: z selects weight/bias/dst. Output [B,H,S,D] bf16. Q pre-scaled.
__global__ void __launch_bounds__(256, 2) gemm_qkv(const float* __restrict__ bq,
                                                   const float* __restrict__ bk,
                                                   const float* __restrict__ bv) {
    extern __shared__ char gsm[];
    int z = blockIdx.z;
    int m0 = blockIdx.y * 128, n0 = blockIdx.x * 128;
    const float* bias = (z == 0) ? bq : (z == 1) ? bk : bv;
    bf16* dst = (z == 0) ? g_q : (z == 1) ? g_k : g_v;
    float qs = (z == 0) ? QPRESCALE : 1.0f;

    float c[2][8][4];
    gemm_core(g_h, g_w + (size_t)z * CC * CC, m0, n0, c, gsm);

    int lane = threadIdx.x & 31;
    int wid = threadIdx.x >> 5;
    int wm = wid >> 1, wn = wid & 1;
#pragma unroll
    for (int mt = 0; mt < 2; mt++) {
        int r0 = m0 + wm * 32 + mt * 16 + (lane >> 2);
        int b0i = r0 >> 11, s0i = r0 & 2047;
        int r1 = r0 + 8;
        int b1i = r1 >> 11, s1i = r1 & 2047;
#pragma unroll
        for (int nt = 0; nt < 8; nt++) {
            int n = n0 + wn * 64 + nt * 8 + (lane & 3) * 2;
            float bv0 = bias[n], bv1 = bias[n + 1];
            int h = n >> 6, d = n & 63;
            uint32_t v0 = pack_bf16x2((c[mt][nt][0] + bv0) * qs, (c[mt][nt][1] + bv1) * qs);
            uint32_t v1 = pack_bf16x2((c[mt][nt][2] + bv0) * qs, (c[mt][nt][3] + bv1) * qs);
            *(uint32_t*)&dst[(((size_t)b0i * HH + h) * SS + s0i) * DD + d] = v0;
            *(uint32_t*)&dst[(((size_t)b1i * HH + h) * SS + s1i) * DD + d] = v1;
        }
    }
}

// Output projection: fp32 out [B,C,S] = A@wo^T + bo + residual
__global__ void __launch_bounds__(256, 2) gemm_out(const float* __restrict__ bias,
                                                   const float* __restrict__ resid,
                                                   float* __restrict__ outp) {
    extern __shared__ char gsm[];
    int m0 = blockIdx.y * 128, n0 = blockIdx.x * 128;

    float c[2][8][4];
    gemm_core(g_o, g_w + (size_t)3 * CC * CC, m0, n0, c, gsm);

    int lane = threadIdx.x & 31;
    int wid = threadIdx.x >> 5;
    int wm = wid >> 1, wn = wid & 1;
#pragma unroll
    for (int mt = 0; mt < 2; mt++) {
        int r0 = m0 + wm * 32 + mt * 16 + (lane >> 2);
#pragma unroll
        for (int half = 0; half < 2; half++) {
            int m = r0 + half * 8;
            int b = m >> 11, s = m & 2047;
#pragma unroll
            for (int nt = 0; nt < 8; nt++) {
                int n = n0 + wn * 64 + nt * 8 + (lane & 3) * 2;
                size_t oi0 = ((size_t)b * CC + n) * SS + s;
                size_t oi1 = oi0 + SS;
                outp[oi0] = c[mt][nt][2 * half + 0] + bias[n]     + resid[oi0];
                outp[oi1] = c[mt][nt][2 * half + 1] + bias[n + 1] + resid[oi1];
            }
        }
    }
}

// ---------------- HMMA flash attention (no-rescale softmax, ex2-only) ------
// CTA = 128 q rows of one (b,h); 8 warps x 16 q rows. 128-key double-buffered
// cp.async K/V tiles. Q pre-scaled by 0.125*log2e -> P = ex2(S).
#define AST 72
#define ATB (128 * AST * 2)           // bytes per tile buffer (18432)
#define A_SMEM_BYTES (5 * ATB)        // Q + K0 + K1 + V0 + V1

__global__ void __launch_bounds__(256, 2) attn_mma() {
    extern __shared__ char asm_[];
    uint32_t sQ = smem_u32(asm_);
    uint32_t sK = sQ + ATB;           // 2 buffers
    uint32_t sV = sQ + 3 * ATB;       // 2 buffers

    int tid = threadIdx.x;
    int lane = tid & 31;
    int wid = tid >> 5;
    int bh = blockIdx.y;
    int q0 = blockIdx.x * 128;

    const bf16* Qg = g_q + ((size_t)bh * SS + q0) * DD;
    const bf16* Kg = g_k + (size_t)bh * SS * DD;
    const bf16* Vg = g_v + (size_t)bh * SS * DD;

    int r = tid >> 1, cseg = (tid & 1) * 32;
    uint32_t dOff = (uint32_t)(r * AST + cseg) * 2;
    const bf16* Kt = Kg + (size_t)r * DD + cseg;
    const bf16* Vt = Vg + (size_t)r * DD + cseg;

    // prefetch K/V tile 0 into buffer 0
#pragma unroll
    for (int j = 0; j < 4; j++) {
        cp16(sK + dOff + j * 16, Kt + j * 8);
        cp16(sV + dOff + j * 16, Vt + j * 8);
    }
    CP_COMMIT();

    // load Q tile [128 x 64]
    {
        const uint4* src = (const uint4*)(Qg + (size_t)r * DD + cseg);
        uint4* dst = (uint4*)(asm_ + dOff);
        dst[0] = src[0]; dst[1] = src[1]; dst[2] = src[2]; dst[3] = src[3];
    }
    __syncthreads();

    // preload Q fragments (constant across key tiles)
    uint32_t aq[4][4];
#pragma unroll
    for (int ks = 0; ks < 4; ks++) {
        uint32_t row = wid * 16 + (lane & 15);
        uint32_t col = ks * 16 + (lane >> 4) * 8;
        ldsm4(aq[ks], sQ + (row * AST + col) * 2);
    }

    float o[8][4];
#pragma unroll
    for (int i = 0; i < 8; i++)
#pragma unroll
        for (int j = 0; j < 4; j++) o[i][j] = 0.f;
    float l0 = 0.f, l1 = 0.f;

    for (int kt = 0; kt < 16; kt++) {
        uint32_t bo = (uint32_t)(kt & 1) * ATB;
        CP_WAIT0();
        __syncthreads();
        if (kt < 15) {
            uint32_t bn = (uint32_t)((kt + 1) & 1) * ATB;
            const bf16* Kn = Kt + (size_t)(kt + 1) * 128 * DD;
            const bf16* Vn = Vt + (size_t)(kt + 1) * 128 * DD;
#pragma unroll
            for (int j = 0; j < 4; j++) {
                cp16(sK + bn + dOff + j * 16, Kn + j * 8);
                cp16(sV + bn + dOff + j * 16, Vn + j * 8);
            }
            CP_COMMIT();
        }

#pragma unroll
        for (int s = 0; s < 8; s++) {
            // S-slab: 16 q rows x 16 keys (scores already in log2 domain)
            float c0[4] = {0.f, 0.f, 0.f, 0.f};
            float c1[4] = {0.f, 0.f, 0.f, 0.f};
#pragma unroll
            for (int ks = 0; ks < 4; ks++) {
                uint32_t t4[4];
                uint32_t row = s * 16 + (lane & 7) + ((lane >> 4) << 3);
                uint32_t col = ks * 16 + (((lane >> 3) & 1) << 3);
                ldsm4(t4, sK + bo + (row * AST + col) * 2);
                mma16816(c0, aq[ks], t4[0], t4[1]);
                mma16816(c1, aq[ks], t4[2], t4[3]);
            }
            float p00 = ex2(c0[0]);
            float p01 = ex2(c0[1]);
            float p02 = ex2(c0[2]);
            float p03 = ex2(c0[3]);
            float p10 = ex2(c1[0]);
            float p11 = ex2(c1[1]);
            float p12 = ex2(c1[2]);
            float p13 = ex2(c1[3]);
            l0 += p00 + p01 + p10 + p11;
            l1 += p02 + p03 + p12 + p13;
            uint32_t ap[4];
            ap[0] = pack_bf16x2(p00, p01);
            ap[1] = pack_bf16x2(p02, p03);
            ap[2] = pack_bf16x2(p10, p11);
            ap[3] = pack_bf16x2(p12, p13);
#pragma unroll
            for (int dp = 0; dp < 4; dp++) {
                uint32_t t4[4];
                uint32_t row = s * 16 + (lane & 15);
                uint32_t col = dp * 16 + (lane >> 4) * 8;
                ldsm4t(t4, sV + bo + (row * AST + col) * 2);
                mma16816(o[2 * dp],     ap, t4[0], t4[1]);
                mma16816(o[2 * dp + 1], ap, t4[2], t4[3]);
            }
        }
    }

    // reduce l over the 4-lane quad (lanes sharing a row)
    l0 += __shfl_xor_sync(0xFFFFFFFF, l0, 1);
    l0 += __shfl_xor_sync(0xFFFFFFFF, l0, 2);
    l1 += __shfl_xor_sync(0xFFFFFFFF, l1, 1);
    l1 += __shfl_xor_sync(0xFFFFFFFF, l1, 2);
    float invl0 = 1.f / l0, invl1 = 1.f / l1;

    // write O as bf16 to g_o [B,S,C]
    int b = bh >> 3, h = bh & 7;
    int row0 = q0 + wid * 16 + (lane >> 2);
    bf16* out0 = g_o + ((size_t)b * SS + row0) * CC + h * DD;
    bf16* out1 = g_o + ((size_t)b * SS + row0 + 8) * CC + h * DD;
#pragma unroll
    for (int nt = 0; nt < 8; nt++) {
        int d = nt * 8 + (lane & 3) * 2;
        *(uint32_t*)&out0[d] = pack_bf16x2(o[nt][0] * invl0, o[nt][1] * invl0);
        *(uint32_t*)&out1[d] = pack_bf16x2(o[nt][2] * invl1, o[nt][3] * invl1);
    }
}

// ---------------- launch ----------------
extern "C" void kernel_launch(void* const* d_in, const int* in_sizes, int n_in,
                              void* d_out, int out_size) {
    const float* x  = (const float*)d_in[0];
    const float* gw = (const float*)d_in[1];
    const float* gb = (const float*)d_in[2];
    const float* wq = (const float*)d_in[3];
    const float* bq = (const float*)d_in[4];
    const float* wk = (const float*)d_in[5];
    const float* bk = (const float*)d_in[6];
    const float* wv = (const float*)d_in[7];
    const float* bv = (const float*)d_in[8];
    const float* wo = (const float*)d_in[9];
    const float* bo = (const float*)d_in[10];
    float* out = (float*)d_out;

    cudaFuncSetAttribute(attn_mma, cudaFuncAttributeMaxDynamicSharedMemorySize, A_SMEM_BYTES);
    cudaFuncSetAttribute(gemm_qkv, cudaFuncAttributeMaxDynamicSharedMemorySize, G_SMEM_BYTES);
    cudaFuncSetAttribute(gemm_out, cudaFuncAttributeMaxDynamicSharedMemorySize, G_SMEM_BYTES);

    gn_partial<<<128, 256>>>(x);
    gn_finalize<<<1, 32>>>();
    norm_convert<<<dim3(SS / 32, CC / 32, BB), dim3(32, 32)>>>(x, gw, gb);
    w_convert<<<CC * CC / 256, 256>>>(wq, wk, wv, wo);

    gemm_qkv<<<dim3(CC / 128, BB * SS / 128, 3), 256, G_SMEM_BYTES>>>(bq, bk, bv);

    attn_mma<<<dim3(SS / 128, BB * HH), 256, A_SMEM_BYTES>>>();

    gemm_out<<<dim3(CC / 128, BB * SS / 128), 256, G_SMEM_BYTES>>>(bo, x, out);
}